// round 3
// baseline (speedup 1.0000x reference)
#include <cuda_runtime.h>
#include <cstdint>

#define N_NODES 50000
#define C 128
#define C4 32  // float4 per row

// ---------------- device scratch (no allocs allowed) ----------------
__device__ float g_agg[(size_t)N_NODES * C];
__device__ float g_h[(size_t)N_NODES * C];
__device__ float g_deg[N_NODES];
__device__ float g_inv[N_NODES];
__device__ int   g_is64;

// ---------------- zero / init ----------------
__global__ void zero_agg_kernel() {
    long long i = (long long)blockIdx.x * blockDim.x + threadIdx.x;
    float4* p = (float4*)g_agg;
    long long n4 = (long long)N_NODES * C4;
    if (i < n4) p[i] = make_float4(0.f, 0.f, 0.f, 0.f);
}

__global__ void init_deg_kernel() {
    int i = blockIdx.x * blockDim.x + threadIdx.x;
    if (i < N_NODES) g_deg[i] = 0.f;
    if (i == 0) g_is64 = 1;
}

// Detect edge_index dtype: check odd 32-bit words of the first `nwords` words.
// int64 data (values in [0,50000)) has ALL high words zero; int32 data has
// real indices there (4096 random values in [0,50000) can't all be zero).
__global__ void detect_kernel(const unsigned int* __restrict__ w, int nwords) {
    int i = blockIdx.x * blockDim.x + threadIdx.x;
    int wi = 2 * i + 1;
    if (wi < nwords && w[wi] != 0u) g_is64 = 0;
}

// ---------------- degree ----------------
__global__ void deg_kernel(const void* __restrict__ ei, int E) {
    int e = blockIdx.x * blockDim.x + threadIdx.x;
    if (e >= E) return;
    int d;
    if (g_is64) d = (int)((const long long*)ei)[(long long)E + e];
    else        d = ((const int*)ei)[E + e];
    atomicAdd(&g_deg[d], 1.0f);
}

__global__ void inv_kernel() {
    int i = blockIdx.x * blockDim.x + threadIdx.x;
    if (i < N_NODES) g_inv[i] = 1.0f / fmaxf(g_deg[i], 1.0f);
}

// ---------------- scatter: agg[dst] += feat[src] ----------------
// One warp per edge; each lane handles one float4 (32 x float4 = 128 floats).
__global__ void scatter_kernel(const float* __restrict__ feat,
                               const void* __restrict__ ei, int E) {
    long long idx = (long long)blockIdx.x * blockDim.x + threadIdx.x;
    int e = (int)(idx >> 5);
    int j = (int)(idx & 31);
    if (e >= E) return;
    int s, d;
    if (g_is64) {
        const long long* p = (const long long*)ei;
        s = (int)p[e];
        d = (int)p[(long long)E + e];
    } else {
        const int* p = (const int*)ei;
        s = p[e];
        d = p[E + e];
    }
    float4 v = ((const float4*)feat)[(long long)s * C4 + j];
    float* dstp = g_agg + (long long)d * C + j * 4;
    asm volatile("red.global.add.v4.f32 [%0], {%1, %2, %3, %4};"
                 :: "l"(__cvta_generic_to_global(dstp)),
                    "f"(v.x), "f"(v.y), "f"(v.z), "f"(v.w)
                 : "memory");
}

// ---------------- fused SAGE GEMM ----------------
// out[n,c] = sum_k mean[n,k]*Wl[c,k] + bl[c] + sum_k xin[n,k]*Wr[c,k]  (+relu)
// As a single GEMM: A = [mean | xin] (50000 x 256), B[k,c] = Wl[c,k] (k<128)
// or Wr[c,k-128]. 128x128x16 tiles, 256 threads, 8x8 per-thread microtile.
#define BM 128
#define BN 128
#define BK 16
#define TM 8
#define TN 8

__global__ __launch_bounds__(256)
void sage_gemm_kernel(const float* __restrict__ xin,
                      const float* __restrict__ Wl,
                      const float* __restrict__ bl,
                      const float* __restrict__ Wr,
                      float* __restrict__ out, int relu) {
    __shared__ float As[BK][BM + 4];
    __shared__ float Bs[BK][BN + 4];

    int t  = threadIdx.x;
    int tx = t & 15;      // 0..15 -> output cols tx*8..+7
    int ty = t >> 4;      // 0..15 -> output rows ty*8..+7
    int bm = blockIdx.x * BM;

    float acc[TM][TN];
#pragma unroll
    for (int i = 0; i < TM; i++)
#pragma unroll
        for (int j = 0; j < TN; j++) acc[i][j] = 0.f;

    const float4* agg4 = (const float4*)g_agg;
    const float4* xin4 = (const float4*)xin;

#pragma unroll 1
    for (int k0 = 0; k0 < 2 * C; k0 += BK) {
        bool first = (k0 < C);
        // ---- load A tile (128 m x 16 k), computing mean on the fly ----
#pragma unroll
        for (int i = 0; i < 2; i++) {
            int lin = t + i * 256;         // 0..511
            int m   = lin >> 2;            // 0..127
            int kq  = lin & 3;             // 0..3 (4 floats each)
            int n   = bm + m;
            if (n >= N_NODES) n = N_NODES - 1;
            float4 v;
            if (first) {
                v = agg4[(long long)n * C4 + ((k0 >> 2) + kq)];
                float s = g_inv[n];
                v.x *= s; v.y *= s; v.z *= s; v.w *= s;
            } else {
                v = xin4[(long long)n * C4 + (((k0 - C) >> 2) + kq)];
            }
            As[kq * 4 + 0][m] = v.x;
            As[kq * 4 + 1][m] = v.y;
            As[kq * 4 + 2][m] = v.z;
            As[kq * 4 + 3][m] = v.w;
        }
        // ---- load B tile (16 k x 128 c): B[k][c] = W[c][k] (transpose) ----
        {
            const float4* W4 = (const float4*)(first ? Wl : Wr);
            int lk0 = first ? k0 : (k0 - C);
#pragma unroll
            for (int i = 0; i < 2; i++) {
                int lin = t + i * 256;
                int c   = lin >> 2;
                int kq  = lin & 3;
                float4 v = W4[c * C4 + ((lk0 >> 2) + kq)];
                Bs[kq * 4 + 0][c] = v.x;
                Bs[kq * 4 + 1][c] = v.y;
                Bs[kq * 4 + 2][c] = v.z;
                Bs[kq * 4 + 3][c] = v.w;
            }
        }
        __syncthreads();
        // ---- compute ----
#pragma unroll
        for (int kk = 0; kk < BK; kk++) {
            float a[TM], b[TN];
            float4 a0 = *(const float4*)&As[kk][ty * TM];
            float4 a1 = *(const float4*)&As[kk][ty * TM + 4];
            float4 b0 = *(const float4*)&Bs[kk][tx * TN];
            float4 b1 = *(const float4*)&Bs[kk][tx * TN + 4];
            a[0]=a0.x; a[1]=a0.y; a[2]=a0.z; a[3]=a0.w;
            a[4]=a1.x; a[5]=a1.y; a[6]=a1.z; a[7]=a1.w;
            b[0]=b0.x; b[1]=b0.y; b[2]=b0.z; b[3]=b0.w;
            b[4]=b1.x; b[5]=b1.y; b[6]=b1.z; b[7]=b1.w;
#pragma unroll
            for (int i = 0; i < TM; i++)
#pragma unroll
                for (int j = 0; j < TN; j++)
                    acc[i][j] = fmaf(a[i], b[j], acc[i][j]);
        }
        __syncthreads();
    }

    // ---- epilogue: add bias, optional relu, store ----
    float bias[TN];
#pragma unroll
    for (int j = 0; j < TN; j++) bias[j] = bl[tx * TN + j];

    float relu_gate = relu ? 1.0f : 0.0f;  // branchless: min-clamp only if relu
#pragma unroll
    for (int i = 0; i < TM; i++) {
        int n = bm + ty * TM + i;
        if (n >= N_NODES) continue;
        float v[TN];
#pragma unroll
        for (int j = 0; j < TN; j++) {
            float xv = acc[i][j] + bias[j];
            // if relu: max(xv,0); else xv.  fmaxf(xv, -inf*0=0? no) -> select
            v[j] = (relu_gate != 0.0f) ? fmaxf(xv, 0.f) : xv;
        }
        float4 o0 = make_float4(v[0], v[1], v[2], v[3]);
        float4 o1 = make_float4(v[4], v[5], v[6], v[7]);
        float4* op = (float4*)(out + (long long)n * C + tx * TN);
        op[0] = o0;
        op[1] = o1;
    }
}

// ---------------- launch ----------------
extern "C" void kernel_launch(void* const* d_in, const int* in_sizes, int n_in,
                              void* d_out, int out_size) {
    const float* x    = (const float*)d_in[0];
    const void*  ei   = d_in[1];
    const float* Wl1  = (const float*)d_in[2];
    const float* bl1  = (const float*)d_in[3];
    const float* Wr1  = (const float*)d_in[4];
    const float* Wl2  = (const float*)d_in[5];
    const float* bl2  = (const float*)d_in[6];
    const float* Wr2  = (const float*)d_in[7];
    float* out = (float*)d_out;

    int E = in_sizes[1] / 2;  // element count is 2*E for both int32 and int64

    long long agg4 = (long long)N_NODES * C4;
    int zero_blocks = (int)((agg4 + 255) / 256);
    int node_blocks = (N_NODES + 255) / 256;
    int edge_blocks = (E + 255) / 256;
    long long sc_threads = (long long)E * 32;
    int sc_blocks = (int)((sc_threads + 255) / 256);
    int gemm_blocks = (N_NODES + BM - 1) / BM;

    // dtype detection window: first 8192 words (or fewer)
    long long total_words_min = (long long)E * 2;
    int nwords = (int)(total_words_min < 8192 ? total_words_min : 8192);
    int det_blocks = (nwords / 2 + 255) / 256;

    // ---- setup ----
    zero_agg_kernel<<<zero_blocks, 256>>>();
    init_deg_kernel<<<node_blocks, 256>>>();
    detect_kernel<<<det_blocks, 256>>>((const unsigned int*)ei, nwords);
    deg_kernel<<<edge_blocks, 256>>>(ei, E);
    inv_kernel<<<node_blocks, 256>>>();

    // ---- layer 1 ----
    scatter_kernel<<<sc_blocks, 256>>>(x, ei, E);
    sage_gemm_kernel<<<gemm_blocks, 256>>>(x, Wl1, bl1, Wr1, g_h, /*relu=*/1);

    // ---- layer 2 ----
    zero_agg_kernel<<<zero_blocks, 256>>>();
    scatter_kernel<<<sc_blocks, 256>>>(g_h, ei, E);
    sage_gemm_kernel<<<gemm_blocks, 256>>>(g_h, Wl2, bl2, Wr2, out, /*relu=*/0);
}